// round 9
// baseline (speedup 1.0000x reference)
#include <cuda_runtime.h>
#include <math.h>
#include <stdint.h>

// ----------------------------------------------------------------------------
// Problem constants
// ----------------------------------------------------------------------------
#define TT   2048
#define BB   32
#define HH   512
#define NB   64              // CTAs per direction
#define CPB  8               // hidden columns per CTA
#define STR  516             // SMEM row stride in floats
#define NG   4               // independent groups per CTA (8 batch rows each)
#define GB   8               // batch rows per group

// ----------------------------------------------------------------------------
// Device scratch: 8 independent barrier networks (2 dirs x 4 groups)
// ----------------------------------------------------------------------------
__device__ float    g_h[2][2][BB * HH];        // [dir][parity][b*H + j]
__device__ unsigned g_grp[2][NG][8];           // tree leaves (8 groups of 8 CTAs)
__device__ unsigned g_root[2][NG];
__device__ unsigned g_gen[2][NG];              // monotonic generations

struct Args {
    const float* x;
    const float* Wxi[2][3];   // [dir][{Wri,Wci,Wni}]  (I x H, row-major)
    const float* Whh[2][3];   // [dir][{Wrh,Wch,Wnh}]  (H x H, row-major)
    const float* br[2];
    const float* bi[2];
    const float* bni[2];
    const float* bnh[2];
    float*       out;
};

// Packed fp32x2 FMA
__device__ __forceinline__ void ffma2(unsigned long long& d,
                                      unsigned long long a, unsigned long long b)
{
    asm("fma.rn.f32x2 %0, %1, %2, %0;" : "+l"(d) : "l"(a), "l"(b));
}
__device__ __forceinline__ float u64lo(unsigned long long v) {
    return __uint_as_float((unsigned)(v & 0xffffffffull));
}
__device__ __forceinline__ float u64hi(unsigned long long v) {
    return __uint_as_float((unsigned)(v >> 32));
}

// Scoped atomics: no full membar (avoids CCTL.IVALL L1 flush per step)
__device__ __forceinline__ unsigned atom_add_acqrel(unsigned* p, unsigned v)
{
    unsigned old;
    asm volatile("atom.acq_rel.gpu.add.u32 %0, [%1], %2;"
                 : "=r"(old) : "l"(p), "r"(v) : "memory");
    return old;
}
__device__ __forceinline__ unsigned ld_acquire(const unsigned* p)
{
    unsigned v;
    asm volatile("ld.acquire.gpu.u32 %0, [%1];" : "=r"(v) : "l"(p) : "memory");
    return v;
}

// Per-network arrive tree (called by group leader only). acq_rel atomics give
// cumulative release ordering: group's h stores (ordered by bar.sync) are
// visible before gen increments.
__device__ __forceinline__ void net_arrive(int d, int g, int grpIdx)
{
    unsigned a = atom_add_acqrel(&g_grp[d][g][grpIdx], 1u);
    if (((a + 1u) & 7u) == 0u) {
        unsigned r = atom_add_acqrel(&g_root[d][g], 1u);
        if (((r + 1u) & 7u) == 0u)
            atom_add_acqrel(&g_gen[d][g], 1u);
    }
}

// Group-scoped named barrier (64 threads, ids 1..4)
#define GBAR(g) asm volatile("bar.sync %0, 64;" :: "r"((g) + 1) : "memory")

// Fast, overflow-safe activations
__device__ __forceinline__ float fast_sigmoid(float z) {
    return __fdividef(1.0f, 1.0f + __expf(-z));
}
__device__ __forceinline__ float fast_tanh(float z) {
    float a = fabsf(z);
    float e = __expf(-2.0f * a);
    float t = __fdividef(1.0f - e, 1.0f + e);
    return copysignf(t, z);
}

// ----------------------------------------------------------------------------
// Fused persistent kernel, 4 independent batch-groups per CTA.
// Group step: stage x -> bar -> x-GEMM -> wait(own net) -> stage h -> bar ->
//             h-GEMM -> reduce -> activations -> store -> bar -> arrive
// ----------------------------------------------------------------------------
__global__ void __launch_bounds__(256, 1) gru_fused(Args p)
{
    extern __shared__ float smem[];
    float* Wx   = smem;                  // [24][STR]  rows: jl*3 + gate
    float* Wh   = Wx + 24 * STR;         // [24][STR]
    float* xbuf = Wh + 24 * STR;         // [32][STR]  (partitioned per group)
    float* hbuf = xbuf + 32 * STR;       // [32][STR]

    const int tid = threadIdx.x;
    const int dir = blockIdx.x / NB;
    const int blk = blockIdx.x % NB;
    const int grpIdx = blk >> 3;
    const int j0  = blk * CPB;

    const int g    = tid >> 6;           // group 0..3
    const int tidg = tid & 63;
    const int s    = tidg & 15;          // k-split lane
    const int jp   = tidg >> 4;          // j-pair 0..3
    const int b0   = g * GB;             // group's batch base
    const bool leader = (tidg == 0);

    // Load + transpose weight slices with all 256 threads
    for (int idx = tid; idx < 3 * HH * CPB; idx += 256) {
        int gg = idx >> 12;
        int k  = (idx >> 3) & (HH - 1);
        int jl = idx & 7;
        Wx[(jl * 3 + gg) * STR + k] = p.Wxi[dir][gg][(size_t)k * HH + j0 + jl];
        Wh[(jl * 3 + gg) * STR + k] = p.Whh[dir][gg][(size_t)k * HH + j0 + jl];
    }
    __syncthreads();

    // each thread owns one (b, j) output
    const int myb  = b0 + (s & 7);
    const int jcol = j0 + jp * 2 + (s >> 3);
    const float c_br  = p.br [dir][jcol];
    const float c_bi  = p.bi [dir][jcol];
    const float c_bni = p.bni[dir][jcol];
    const float c_bnh = p.bnh[dir][jcol];

    unsigned base = 0;
    if (leader) base = ld_acquire(&g_gen[dir][g]);

    // h0 = 0
    g_h[dir][0][myb * HH + jcol] = 0.0f;
    GBAR(g);
    if (leader) net_arrive(dir, g, grpIdx);

    const float* WxB = &Wx[jp * 6 * STR];
    const float* WhB = &Wh[jp * 6 * STR];
    float* out = p.out;

#define GEMM_ITER(WB, BUF, c0, c1, c2)                                          \
    {                                                                           \
        const int kk = (s << 2) + (i << 6);                                     \
        ulonglong2 w0 = *(const ulonglong2*)&WB[0 * STR + kk];                  \
        ulonglong2 w1 = *(const ulonglong2*)&WB[1 * STR + kk];                  \
        ulonglong2 w2 = *(const ulonglong2*)&WB[2 * STR + kk];                  \
        ulonglong2 w3 = *(const ulonglong2*)&WB[3 * STR + kk];                  \
        ulonglong2 w4 = *(const ulonglong2*)&WB[4 * STR + kk];                  \
        ulonglong2 w5 = *(const ulonglong2*)&WB[5 * STR + kk];                  \
        _Pragma("unroll")                                                       \
        for (int bb = 0; bb < 8; ++bb) {                                        \
            ulonglong2 v = *(const ulonglong2*)&BUF[(b0 + bb) * STR + kk];      \
            ffma2(acc[bb][c0],     v.x, w0.x);  ffma2(acc[bb][c0],     v.y, w0.y); \
            ffma2(acc[bb][c1],     v.x, w1.x);  ffma2(acc[bb][c1],     v.y, w1.y); \
            ffma2(acc[bb][c2],     v.x, w2.x);  ffma2(acc[bb][c2],     v.y, w2.y); \
            ffma2(acc[bb][4 + c0], v.x, w3.x);  ffma2(acc[bb][4 + c0], v.y, w3.y); \
            ffma2(acc[bb][4 + c1], v.x, w4.x);  ffma2(acc[bb][4 + c1], v.y, w4.y); \
            ffma2(acc[bb][4 + c2], v.x, w5.x);  ffma2(acc[bb][4 + c2], v.y, w5.y); \
        }                                                                       \
    }

    for (int st = 0; st < TT; ++st) {
        const int t   = dir ? (TT - 1 - st) : st;
        const int par = st & 1;

        // ---- stage x(t) rows [b0, b0+8) -> xbuf ----
        {
            const float* xrowbase = p.x + ((size_t)t * BB + b0) * HH;
            #pragma unroll
            for (int r = 0; r < 16; ++r) {
                int idx = tidg + r * 64;           // 1024 float4s for the group
                int row = idx >> 7;                // 0..7
                int kk  = (idx & 127) << 2;
                float4 v = __ldg((const float4*)(xrowbase + (size_t)row * HH + kk));
                *(float4*)&xbuf[(b0 + row) * STR + kk] = v;
            }
        }
        GBAR(g);

        // accumulators: [bb][jj*4 + ch], ch: 0=r, 1=c, 2=n_x, 3=n_h
        unsigned long long acc[8][8];
        #pragma unroll
        for (int bb = 0; bb < 8; ++bb)
            #pragma unroll
            for (int q = 0; q < 8; ++q) acc[bb][q] = 0ull;

        // ---- x-GEMM (hides own-network barrier latency) ----
        #pragma unroll
        for (int i = 0; i < 8; ++i) GEMM_ITER(WxB, xbuf, 0, 1, 2)

        // ---- wait for h(t) on this group's network ----
        if (leader) {
            while (ld_acquire(&g_gen[dir][g]) - base < (unsigned)(st + 1)) { }
        }
        GBAR(g);

        // ---- stage h(t) rows [b0, b0+8) -> hbuf (L2-coherent loads) ----
        {
            const float* hrowbase = (const float*)g_h[dir][par] + (size_t)b0 * HH;
            #pragma unroll
            for (int r = 0; r < 16; ++r) {
                int idx = tidg + r * 64;
                int row = idx >> 7;
                int kk  = (idx & 127) << 2;
                float4 v = __ldcv((const float4*)(hrowbase + (size_t)row * HH + kk));
                *(float4*)&hbuf[(b0 + row) * STR + kk] = v;
            }
        }
        GBAR(g);

        // ---- h-GEMM ----
        #pragma unroll
        for (int i = 0; i < 8; ++i) GEMM_ITER(WhB, hbuf, 0, 1, 3)

        // ---- collapse f32x2 pairs ----
        float a64[8][8];
        #pragma unroll
        for (int bb = 0; bb < 8; ++bb)
            #pragma unroll
            for (int q = 0; q < 8; ++q)
                a64[bb][q] = u64lo(acc[bb][q]) + u64hi(acc[bb][q]);

        // ---- targeted exchange reduction over the 16 k-split lanes ----
        const bool hi8 = (s & 8) != 0;
        float r32[8][4];
        #pragma unroll
        for (int bb = 0; bb < 8; ++bb)
            #pragma unroll
            for (int ch = 0; ch < 4; ++ch) {
                float mine = hi8 ? a64[bb][4 + ch] : a64[bb][ch];
                float oth  = hi8 ? a64[bb][ch]     : a64[bb][4 + ch];
                r32[bb][ch] = mine + __shfl_xor_sync(0xffffffffu, oth, 8);
            }
        const bool hi4 = (s & 4) != 0;
        float r16[4][4];
        #pragma unroll
        for (int bl = 0; bl < 4; ++bl)
            #pragma unroll
            for (int ch = 0; ch < 4; ++ch) {
                float mine = hi4 ? r32[bl + 4][ch] : r32[bl][ch];
                float oth  = hi4 ? r32[bl][ch]     : r32[bl + 4][ch];
                r16[bl][ch] = mine + __shfl_xor_sync(0xffffffffu, oth, 4);
            }
        const bool hi2 = (s & 2) != 0;
        float r8[2][4];
        #pragma unroll
        for (int bl = 0; bl < 2; ++bl)
            #pragma unroll
            for (int ch = 0; ch < 4; ++ch) {
                float mine = hi2 ? r16[bl + 2][ch] : r16[bl][ch];
                float oth  = hi2 ? r16[bl][ch]     : r16[bl + 2][ch];
                r8[bl][ch] = mine + __shfl_xor_sync(0xffffffffu, oth, 2);
            }
        const bool hi1 = (s & 1) != 0;
        float r4v[4];
        #pragma unroll
        for (int ch = 0; ch < 4; ++ch) {
            float mine = hi1 ? r8[1][ch] : r8[0][ch];
            float oth  = hi1 ? r8[0][ch] : r8[1][ch];
            r4v[ch] = mine + __shfl_xor_sync(0xffffffffu, oth, 1);
        }

        // ---- activations + state update ----
        const float rg = fast_sigmoid(r4v[0] + c_br);
        const float cg = fast_sigmoid(r4v[1] + c_bi);
        const float ng = fast_tanh(r4v[2] + c_bni + rg * (r4v[3] + c_bnh));
        const float hold = hbuf[myb * STR + jcol];
        const float hnew = ng + cg * (hold - ng);

        g_h[dir][par ^ 1][myb * HH + jcol] = hnew;
        out[((size_t)t * BB + myb) * (2 * HH) + dir * HH + jcol] = hnew;

        GBAR(g);                              // group stores complete
        if (leader) net_arrive(dir, g, grpIdx);
    }
#undef GEMM_ITER
}

// ----------------------------------------------------------------------------
// Launch. Input order: x, Wri_f,Wci_f,Wni_f,Wrh_f,Wch_f,Wnh_f,br_f,bi_f,bni_f,
// bnh_f, Wri_b,Wci_b,Wni_b,Wrh_b,Wch_b,Wnh_b,br_b,bi_b,bni_b,bnh_b
// ----------------------------------------------------------------------------
extern "C" void kernel_launch(void* const* d_in, const int* in_sizes, int n_in,
                              void* d_out, int out_size)
{
    (void)in_sizes; (void)n_in; (void)out_size;

    Args a;
    a.x = (const float*)d_in[0];
    a.Wxi[0][0] = (const float*)d_in[1];
    a.Wxi[0][1] = (const float*)d_in[2];
    a.Wxi[0][2] = (const float*)d_in[3];
    a.Whh[0][0] = (const float*)d_in[4];
    a.Whh[0][1] = (const float*)d_in[5];
    a.Whh[0][2] = (const float*)d_in[6];
    a.br [0] = (const float*)d_in[7];
    a.bi [0] = (const float*)d_in[8];
    a.bni[0] = (const float*)d_in[9];
    a.bnh[0] = (const float*)d_in[10];
    a.Wxi[1][0] = (const float*)d_in[11];
    a.Wxi[1][1] = (const float*)d_in[12];
    a.Wxi[1][2] = (const float*)d_in[13];
    a.Whh[1][0] = (const float*)d_in[14];
    a.Whh[1][1] = (const float*)d_in[15];
    a.Whh[1][2] = (const float*)d_in[16];
    a.br [1] = (const float*)d_in[17];
    a.bi [1] = (const float*)d_in[18];
    a.bni[1] = (const float*)d_in[19];
    a.bnh[1] = (const float*)d_in[20];
    a.out = (float*)d_out;

    const int smem = (48 * STR + 64 * STR) * (int)sizeof(float);   // ~226 KB
    cudaFuncSetAttribute(gru_fused, cudaFuncAttributeMaxDynamicSharedMemorySize, smem);
    gru_fused<<<2 * NB, 256, smem>>>(a);
}

// round 10
// speedup vs baseline: 1.0012x; 1.0012x over previous
#include <cuda_runtime.h>
#include <math.h>
#include <stdint.h>

// ----------------------------------------------------------------------------
// Problem constants
// ----------------------------------------------------------------------------
#define TT   2048
#define BB   32
#define HH   512
#define NB   64              // CTAs per direction
#define CPB  8               // hidden columns per CTA
#define STR  516             // SMEM row stride in floats
#define NG   4               // independent groups per CTA (8 batch rows each)
#define GB   8               // batch rows per group

// ----------------------------------------------------------------------------
// Device scratch: 8 independent barrier networks (2 dirs x 4 groups)
// ----------------------------------------------------------------------------
__device__ float    g_h[2][2][BB * HH];        // [dir][parity][b*H + j]
__device__ unsigned g_grp[2][NG][8];           // tree leaves (8 groups of 8 CTAs)
__device__ unsigned g_root[2][NG];
__device__ unsigned g_gen[2][NG];              // monotonic generations

struct Args {
    const float* x;
    const float* Wxi[2][3];   // [dir][{Wri,Wci,Wni}]  (I x H, row-major)
    const float* Whh[2][3];   // [dir][{Wrh,Wch,Wnh}]  (H x H, row-major)
    const float* br[2];
    const float* bi[2];
    const float* bni[2];
    const float* bnh[2];
    float*       out;
};

// Packed fp32x2 FMA
__device__ __forceinline__ void ffma2(unsigned long long& d,
                                      unsigned long long a, unsigned long long b)
{
    asm("fma.rn.f32x2 %0, %1, %2, %0;" : "+l"(d) : "l"(a), "l"(b));
}
__device__ __forceinline__ float u64lo(unsigned long long v) {
    return __uint_as_float((unsigned)(v & 0xffffffffull));
}
__device__ __forceinline__ float u64hi(unsigned long long v) {
    return __uint_as_float((unsigned)(v >> 32));
}

// Scoped atomics: no full membar (avoids CCTL.IVALL L1 flush per step)
__device__ __forceinline__ unsigned atom_add_acqrel(unsigned* p, unsigned v)
{
    unsigned old;
    asm volatile("atom.acq_rel.gpu.add.u32 %0, [%1], %2;"
                 : "=r"(old) : "l"(p), "r"(v) : "memory");
    return old;
}
__device__ __forceinline__ unsigned ld_acquire(const unsigned* p)
{
    unsigned v;
    asm volatile("ld.acquire.gpu.u32 %0, [%1];" : "=r"(v) : "l"(p) : "memory");
    return v;
}

// Per-network arrive tree (called by group leader only). acq_rel atomics give
// cumulative release ordering: group's h stores (ordered by bar.sync) are
// visible before gen increments.
__device__ __forceinline__ void net_arrive(int d, int g, int grpIdx)
{
    unsigned a = atom_add_acqrel(&g_grp[d][g][grpIdx], 1u);
    if (((a + 1u) & 7u) == 0u) {
        unsigned r = atom_add_acqrel(&g_root[d][g], 1u);
        if (((r + 1u) & 7u) == 0u)
            atom_add_acqrel(&g_gen[d][g], 1u);
    }
}

// Group-scoped named barrier (64 threads, ids 1..4)
#define GBAR(g) asm volatile("bar.sync %0, 64;" :: "r"((g) + 1) : "memory")

// Fast, overflow-safe activations
__device__ __forceinline__ float fast_sigmoid(float z) {
    return __fdividef(1.0f, 1.0f + __expf(-z));
}
__device__ __forceinline__ float fast_tanh(float z) {
    float a = fabsf(z);
    float e = __expf(-2.0f * a);
    float t = __fdividef(1.0f - e, 1.0f + e);
    return copysignf(t, z);
}

// ----------------------------------------------------------------------------
// Fused persistent kernel, 4 independent batch-groups per CTA.
// Group step: stage x -> bar -> x-GEMM -> wait(own net) -> stage h -> bar ->
//             h-GEMM -> reduce -> activations -> store -> bar -> arrive
// ----------------------------------------------------------------------------
__global__ void __launch_bounds__(256, 1) gru_fused(Args p)
{
    extern __shared__ float smem[];
    float* Wx   = smem;                  // [24][STR]  rows: jl*3 + gate
    float* Wh   = Wx + 24 * STR;         // [24][STR]
    float* xbuf = Wh + 24 * STR;         // [32][STR]  (partitioned per group)
    float* hbuf = xbuf + 32 * STR;       // [32][STR]

    const int tid = threadIdx.x;
    const int dir = blockIdx.x / NB;
    const int blk = blockIdx.x % NB;
    const int grpIdx = blk >> 3;
    const int j0  = blk * CPB;

    const int g    = tid >> 6;           // group 0..3
    const int tidg = tid & 63;
    const int s    = tidg & 15;          // k-split lane
    const int jp   = tidg >> 4;          // j-pair 0..3
    const int b0   = g * GB;             // group's batch base
    const bool leader = (tidg == 0);

    // Load + transpose weight slices with all 256 threads
    for (int idx = tid; idx < 3 * HH * CPB; idx += 256) {
        int gg = idx >> 12;
        int k  = (idx >> 3) & (HH - 1);
        int jl = idx & 7;
        Wx[(jl * 3 + gg) * STR + k] = p.Wxi[dir][gg][(size_t)k * HH + j0 + jl];
        Wh[(jl * 3 + gg) * STR + k] = p.Whh[dir][gg][(size_t)k * HH + j0 + jl];
    }
    __syncthreads();

    // each thread owns one (b, j) output
    const int myb  = b0 + (s & 7);
    const int jcol = j0 + jp * 2 + (s >> 3);
    const float c_br  = p.br [dir][jcol];
    const float c_bi  = p.bi [dir][jcol];
    const float c_bni = p.bni[dir][jcol];
    const float c_bnh = p.bnh[dir][jcol];

    unsigned base = 0;
    if (leader) base = ld_acquire(&g_gen[dir][g]);

    // h0 = 0
    g_h[dir][0][myb * HH + jcol] = 0.0f;
    GBAR(g);
    if (leader) net_arrive(dir, g, grpIdx);

    const float* WxB = &Wx[jp * 6 * STR];
    const float* WhB = &Wh[jp * 6 * STR];
    float* out = p.out;

#define GEMM_ITER(WB, BUF, c0, c1, c2)                                          \
    {                                                                           \
        const int kk = (s << 2) + (i << 6);                                     \
        ulonglong2 w0 = *(const ulonglong2*)&WB[0 * STR + kk];                  \
        ulonglong2 w1 = *(const ulonglong2*)&WB[1 * STR + kk];                  \
        ulonglong2 w2 = *(const ulonglong2*)&WB[2 * STR + kk];                  \
        ulonglong2 w3 = *(const ulonglong2*)&WB[3 * STR + kk];                  \
        ulonglong2 w4 = *(const ulonglong2*)&WB[4 * STR + kk];                  \
        ulonglong2 w5 = *(const ulonglong2*)&WB[5 * STR + kk];                  \
        _Pragma("unroll")                                                       \
        for (int bb = 0; bb < 8; ++bb) {                                        \
            ulonglong2 v = *(const ulonglong2*)&BUF[(b0 + bb) * STR + kk];      \
            ffma2(acc[bb][c0],     v.x, w0.x);  ffma2(acc[bb][c0],     v.y, w0.y); \
            ffma2(acc[bb][c1],     v.x, w1.x);  ffma2(acc[bb][c1],     v.y, w1.y); \
            ffma2(acc[bb][c2],     v.x, w2.x);  ffma2(acc[bb][c2],     v.y, w2.y); \
            ffma2(acc[bb][4 + c0], v.x, w3.x);  ffma2(acc[bb][4 + c0], v.y, w3.y); \
            ffma2(acc[bb][4 + c1], v.x, w4.x);  ffma2(acc[bb][4 + c1], v.y, w4.y); \
            ffma2(acc[bb][4 + c2], v.x, w5.x);  ffma2(acc[bb][4 + c2], v.y, w5.y); \
        }                                                                       \
    }

    for (int st = 0; st < TT; ++st) {
        const int t   = dir ? (TT - 1 - st) : st;
        const int par = st & 1;

        // ---- stage x(t) rows [b0, b0+8) -> xbuf ----
        {
            const float* xrowbase = p.x + ((size_t)t * BB + b0) * HH;
            #pragma unroll
            for (int r = 0; r < 16; ++r) {
                int idx = tidg + r * 64;           // 1024 float4s for the group
                int row = idx >> 7;                // 0..7
                int kk  = (idx & 127) << 2;
                float4 v = __ldg((const float4*)(xrowbase + (size_t)row * HH + kk));
                *(float4*)&xbuf[(b0 + row) * STR + kk] = v;
            }
        }
        GBAR(g);

        // accumulators: [bb][jj*4 + ch], ch: 0=r, 1=c, 2=n_x, 3=n_h
        unsigned long long acc[8][8];
        #pragma unroll
        for (int bb = 0; bb < 8; ++bb)
            #pragma unroll
            for (int q = 0; q < 8; ++q) acc[bb][q] = 0ull;

        // ---- x-GEMM (hides own-network barrier latency) ----
        #pragma unroll
        for (int i = 0; i < 8; ++i) GEMM_ITER(WxB, xbuf, 0, 1, 2)

        // ---- wait for h(t) on this group's network ----
        if (leader) {
            while (ld_acquire(&g_gen[dir][g]) - base < (unsigned)(st + 1)) { }
        }
        GBAR(g);

        // ---- stage h(t) rows [b0, b0+8) -> hbuf (L2-coherent loads) ----
        {
            const float* hrowbase = (const float*)g_h[dir][par] + (size_t)b0 * HH;
            #pragma unroll
            for (int r = 0; r < 16; ++r) {
                int idx = tidg + r * 64;
                int row = idx >> 7;
                int kk  = (idx & 127) << 2;
                float4 v = __ldcv((const float4*)(hrowbase + (size_t)row * HH + kk));
                *(float4*)&hbuf[(b0 + row) * STR + kk] = v;
            }
        }
        GBAR(g);

        // ---- h-GEMM ----
        #pragma unroll
        for (int i = 0; i < 8; ++i) GEMM_ITER(WhB, hbuf, 0, 1, 3)

        // ---- collapse f32x2 pairs ----
        float a64[8][8];
        #pragma unroll
        for (int bb = 0; bb < 8; ++bb)
            #pragma unroll
            for (int q = 0; q < 8; ++q)
                a64[bb][q] = u64lo(acc[bb][q]) + u64hi(acc[bb][q]);

        // ---- targeted exchange reduction over the 16 k-split lanes ----
        const bool hi8 = (s & 8) != 0;
        float r32[8][4];
        #pragma unroll
        for (int bb = 0; bb < 8; ++bb)
            #pragma unroll
            for (int ch = 0; ch < 4; ++ch) {
                float mine = hi8 ? a64[bb][4 + ch] : a64[bb][ch];
                float oth  = hi8 ? a64[bb][ch]     : a64[bb][4 + ch];
                r32[bb][ch] = mine + __shfl_xor_sync(0xffffffffu, oth, 8);
            }
        const bool hi4 = (s & 4) != 0;
        float r16[4][4];
        #pragma unroll
        for (int bl = 0; bl < 4; ++bl)
            #pragma unroll
            for (int ch = 0; ch < 4; ++ch) {
                float mine = hi4 ? r32[bl + 4][ch] : r32[bl][ch];
                float oth  = hi4 ? r32[bl][ch]     : r32[bl + 4][ch];
                r16[bl][ch] = mine + __shfl_xor_sync(0xffffffffu, oth, 4);
            }
        const bool hi2 = (s & 2) != 0;
        float r8[2][4];
        #pragma unroll
        for (int bl = 0; bl < 2; ++bl)
            #pragma unroll
            for (int ch = 0; ch < 4; ++ch) {
                float mine = hi2 ? r16[bl + 2][ch] : r16[bl][ch];
                float oth  = hi2 ? r16[bl][ch]     : r16[bl + 2][ch];
                r8[bl][ch] = mine + __shfl_xor_sync(0xffffffffu, oth, 2);
            }
        const bool hi1 = (s & 1) != 0;
        float r4v[4];
        #pragma unroll
        for (int ch = 0; ch < 4; ++ch) {
            float mine = hi1 ? r8[1][ch] : r8[0][ch];
            float oth  = hi1 ? r8[0][ch] : r8[1][ch];
            r4v[ch] = mine + __shfl_xor_sync(0xffffffffu, oth, 1);
        }

        // ---- activations + state update ----
        const float rg = fast_sigmoid(r4v[0] + c_br);
        const float cg = fast_sigmoid(r4v[1] + c_bi);
        const float ng = fast_tanh(r4v[2] + c_bni + rg * (r4v[3] + c_bnh));
        const float hold = hbuf[myb * STR + jcol];
        const float hnew = ng + cg * (hold - ng);

        g_h[dir][par ^ 1][myb * HH + jcol] = hnew;
        out[((size_t)t * BB + myb) * (2 * HH) + dir * HH + jcol] = hnew;

        GBAR(g);                              // group stores complete
        if (leader) net_arrive(dir, g, grpIdx);
    }
#undef GEMM_ITER
}

// ----------------------------------------------------------------------------
// Launch. Input order: x, Wri_f,Wci_f,Wni_f,Wrh_f,Wch_f,Wnh_f,br_f,bi_f,bni_f,
// bnh_f, Wri_b,Wci_b,Wni_b,Wrh_b,Wch_b,Wnh_b,br_b,bi_b,bni_b,bnh_b
// ----------------------------------------------------------------------------
extern "C" void kernel_launch(void* const* d_in, const int* in_sizes, int n_in,
                              void* d_out, int out_size)
{
    (void)in_sizes; (void)n_in; (void)out_size;

    Args a;
    a.x = (const float*)d_in[0];
    a.Wxi[0][0] = (const float*)d_in[1];
    a.Wxi[0][1] = (const float*)d_in[2];
    a.Wxi[0][2] = (const float*)d_in[3];
    a.Whh[0][0] = (const float*)d_in[4];
    a.Whh[0][1] = (const float*)d_in[5];
    a.Whh[0][2] = (const float*)d_in[6];
    a.br [0] = (const float*)d_in[7];
    a.bi [0] = (const float*)d_in[8];
    a.bni[0] = (const float*)d_in[9];
    a.bnh[0] = (const float*)d_in[10];
    a.Wxi[1][0] = (const float*)d_in[11];
    a.Wxi[1][1] = (const float*)d_in[12];
    a.Wxi[1][2] = (const float*)d_in[13];
    a.Whh[1][0] = (const float*)d_in[14];
    a.Whh[1][1] = (const float*)d_in[15];
    a.Whh[1][2] = (const float*)d_in[16];
    a.br [1] = (const float*)d_in[17];
    a.bi [1] = (const float*)d_in[18];
    a.bni[1] = (const float*)d_in[19];
    a.bnh[1] = (const float*)d_in[20];
    a.out = (float*)d_out;

    const int smem = (48 * STR + 64 * STR) * (int)sizeof(float);   // ~226 KB
    cudaFuncSetAttribute(gru_fused, cudaFuncAttributeMaxDynamicSharedMemorySize, smem);
    gru_fused<<<2 * NB, 256, smem>>>(a);
}

// round 11
// speedup vs baseline: 1.0049x; 1.0038x over previous
#include <cuda_runtime.h>
#include <math.h>
#include <stdint.h>

// ----------------------------------------------------------------------------
// Problem constants
// ----------------------------------------------------------------------------
#define TT   2048
#define BB   32
#define HH   512
#define NB   64              // CTAs per direction
#define CPB  8               // hidden columns per CTA
#define STR  516             // SMEM row stride in floats
#define NG   4               // independent groups per CTA (8 batch rows each)
#define GB   8               // batch rows per group

// ----------------------------------------------------------------------------
// Device scratch: 8 independent barrier networks (2 dirs x 4 groups)
// ----------------------------------------------------------------------------
__device__ float    g_h[2][2][BB * HH];        // [dir][parity][b*H + j]
__device__ unsigned g_grp[2][NG][8];           // tree leaves (8 groups of 8 CTAs)
__device__ unsigned g_root[2][NG];
__device__ unsigned g_gen[2][NG];              // monotonic generations

struct Args {
    const float* x;
    const float* Wxi[2][3];   // [dir][{Wri,Wci,Wni}]  (I x H, row-major)
    const float* Whh[2][3];   // [dir][{Wrh,Wch,Wnh}]  (H x H, row-major)
    const float* br[2];
    const float* bi[2];
    const float* bni[2];
    const float* bnh[2];
    float*       out;
};

// Packed fp32x2 FMA
__device__ __forceinline__ void ffma2(unsigned long long& d,
                                      unsigned long long a, unsigned long long b)
{
    asm("fma.rn.f32x2 %0, %1, %2, %0;" : "+l"(d) : "l"(a), "l"(b));
}
__device__ __forceinline__ float u64lo(unsigned long long v) {
    return __uint_as_float((unsigned)(v & 0xffffffffull));
}
__device__ __forceinline__ float u64hi(unsigned long long v) {
    return __uint_as_float((unsigned)(v >> 32));
}

// Scoped atomics: no full membar (avoids CCTL.IVALL L1 flush per step)
__device__ __forceinline__ unsigned atom_add_acqrel(unsigned* p, unsigned v)
{
    unsigned old;
    asm volatile("atom.acq_rel.gpu.add.u32 %0, [%1], %2;"
                 : "=r"(old) : "l"(p), "r"(v) : "memory");
    return old;
}
__device__ __forceinline__ unsigned ld_acquire(const unsigned* p)
{
    unsigned v;
    asm volatile("ld.acquire.gpu.u32 %0, [%1];" : "=r"(v) : "l"(p) : "memory");
    return v;
}

// Per-network arrive tree (called by group leader only). acq_rel atomics give
// cumulative release ordering: group's h stores (ordered by bar.sync) are
// visible before gen increments.
__device__ __forceinline__ void net_arrive(int d, int g, int grpIdx)
{
    unsigned a = atom_add_acqrel(&g_grp[d][g][grpIdx], 1u);
    if (((a + 1u) & 7u) == 0u) {
        unsigned r = atom_add_acqrel(&g_root[d][g], 1u);
        if (((r + 1u) & 7u) == 0u)
            atom_add_acqrel(&g_gen[d][g], 1u);
    }
}

// Group-scoped named barrier (64 threads, ids 1..4)
#define GBAR(g) asm volatile("bar.sync %0, 64;" :: "r"((g) + 1) : "memory")

// Fast, overflow-safe activations
__device__ __forceinline__ float fast_sigmoid(float z) {
    return __fdividef(1.0f, 1.0f + __expf(-z));
}
__device__ __forceinline__ float fast_tanh(float z) {
    float a = fabsf(z);
    float e = __expf(-2.0f * a);
    float t = __fdividef(1.0f - e, 1.0f + e);
    return copysignf(t, z);
}

// ----------------------------------------------------------------------------
// Fused persistent kernel, 4 independent batch-groups per CTA.
// Group step: stage x -> bar -> x-GEMM -> wait(own net) -> stage h -> bar ->
//             h-GEMM -> reduce -> activations -> store -> bar -> arrive
// ----------------------------------------------------------------------------
__global__ void __launch_bounds__(256, 1) gru_fused(Args p)
{
    extern __shared__ float smem[];
    float* Wx   = smem;                  // [24][STR]  rows: jl*3 + gate
    float* Wh   = Wx + 24 * STR;         // [24][STR]
    float* xbuf = Wh + 24 * STR;         // [32][STR]  (partitioned per group)
    float* hbuf = xbuf + 32 * STR;       // [32][STR]

    const int tid = threadIdx.x;
    const int dir = blockIdx.x / NB;
    const int blk = blockIdx.x % NB;
    const int grpIdx = blk >> 3;
    const int j0  = blk * CPB;

    const int g    = tid >> 6;           // group 0..3
    const int tidg = tid & 63;
    const int s    = tidg & 15;          // k-split lane
    const int jp   = tidg >> 4;          // j-pair 0..3
    const int b0   = g * GB;             // group's batch base
    const bool leader = (tidg == 0);

    // Load + transpose weight slices with all 256 threads
    for (int idx = tid; idx < 3 * HH * CPB; idx += 256) {
        int gg = idx >> 12;
        int k  = (idx >> 3) & (HH - 1);
        int jl = idx & 7;
        Wx[(jl * 3 + gg) * STR + k] = p.Wxi[dir][gg][(size_t)k * HH + j0 + jl];
        Wh[(jl * 3 + gg) * STR + k] = p.Whh[dir][gg][(size_t)k * HH + j0 + jl];
    }
    __syncthreads();

    // each thread owns one (b, j) output
    const int myb  = b0 + (s & 7);
    const int jcol = j0 + jp * 2 + (s >> 3);
    const float c_br  = p.br [dir][jcol];
    const float c_bi  = p.bi [dir][jcol];
    const float c_bni = p.bni[dir][jcol];
    const float c_bnh = p.bnh[dir][jcol];

    unsigned base = 0;
    if (leader) base = ld_acquire(&g_gen[dir][g]);

    // h0 = 0
    g_h[dir][0][myb * HH + jcol] = 0.0f;
    GBAR(g);
    if (leader) net_arrive(dir, g, grpIdx);

    const float* WxB = &Wx[jp * 6 * STR];
    const float* WhB = &Wh[jp * 6 * STR];
    float* out = p.out;

#define GEMM_ITER(WB, BUF, c0, c1, c2)                                          \
    {                                                                           \
        const int kk = (s << 2) + (i << 6);                                     \
        ulonglong2 w0 = *(const ulonglong2*)&WB[0 * STR + kk];                  \
        ulonglong2 w1 = *(const ulonglong2*)&WB[1 * STR + kk];                  \
        ulonglong2 w2 = *(const ulonglong2*)&WB[2 * STR + kk];                  \
        ulonglong2 w3 = *(const ulonglong2*)&WB[3 * STR + kk];                  \
        ulonglong2 w4 = *(const ulonglong2*)&WB[4 * STR + kk];                  \
        ulonglong2 w5 = *(const ulonglong2*)&WB[5 * STR + kk];                  \
        _Pragma("unroll")                                                       \
        for (int bb = 0; bb < 8; ++bb) {                                        \
            ulonglong2 v = *(const ulonglong2*)&BUF[(b0 + bb) * STR + kk];      \
            ffma2(acc[bb][c0],     v.x, w0.x);  ffma2(acc[bb][c0],     v.y, w0.y); \
            ffma2(acc[bb][c1],     v.x, w1.x);  ffma2(acc[bb][c1],     v.y, w1.y); \
            ffma2(acc[bb][c2],     v.x, w2.x);  ffma2(acc[bb][c2],     v.y, w2.y); \
            ffma2(acc[bb][4 + c0], v.x, w3.x);  ffma2(acc[bb][4 + c0], v.y, w3.y); \
            ffma2(acc[bb][4 + c1], v.x, w4.x);  ffma2(acc[bb][4 + c1], v.y, w4.y); \
            ffma2(acc[bb][4 + c2], v.x, w5.x);  ffma2(acc[bb][4 + c2], v.y, w5.y); \
        }                                                                       \
    }

    for (int st = 0; st < TT; ++st) {
        const int t   = dir ? (TT - 1 - st) : st;
        const int par = st & 1;

        // ---- stage x(t) rows [b0, b0+8) -> xbuf ----
        {
            const float* xrowbase = p.x + ((size_t)t * BB + b0) * HH;
            #pragma unroll
            for (int r = 0; r < 16; ++r) {
                int idx = tidg + r * 64;           // 1024 float4s for the group
                int row = idx >> 7;                // 0..7
                int kk  = (idx & 127) << 2;
                float4 v = __ldg((const float4*)(xrowbase + (size_t)row * HH + kk));
                *(float4*)&xbuf[(b0 + row) * STR + kk] = v;
            }
        }
        GBAR(g);

        // accumulators: [bb][jj*4 + ch], ch: 0=r, 1=c, 2=n_x, 3=n_h
        unsigned long long acc[8][8];
        #pragma unroll
        for (int bb = 0; bb < 8; ++bb)
            #pragma unroll
            for (int q = 0; q < 8; ++q) acc[bb][q] = 0ull;

        // ---- x-GEMM (hides own-network barrier latency) ----
        #pragma unroll
        for (int i = 0; i < 8; ++i) GEMM_ITER(WxB, xbuf, 0, 1, 2)

        // ---- wait for h(t) on this group's network ----
        if (leader) {
            while (ld_acquire(&g_gen[dir][g]) - base < (unsigned)(st + 1)) { }
        }
        GBAR(g);

        // ---- stage h(t) rows [b0, b0+8) -> hbuf (L2-coherent loads) ----
        {
            const float* hrowbase = (const float*)g_h[dir][par] + (size_t)b0 * HH;
            #pragma unroll
            for (int r = 0; r < 16; ++r) {
                int idx = tidg + r * 64;
                int row = idx >> 7;
                int kk  = (idx & 127) << 2;
                float4 v = __ldcv((const float4*)(hrowbase + (size_t)row * HH + kk));
                *(float4*)&hbuf[(b0 + row) * STR + kk] = v;
            }
        }
        GBAR(g);

        // ---- h-GEMM ----
        #pragma unroll
        for (int i = 0; i < 8; ++i) GEMM_ITER(WhB, hbuf, 0, 1, 3)

        // ---- collapse f32x2 pairs ----
        float a64[8][8];
        #pragma unroll
        for (int bb = 0; bb < 8; ++bb)
            #pragma unroll
            for (int q = 0; q < 8; ++q)
                a64[bb][q] = u64lo(acc[bb][q]) + u64hi(acc[bb][q]);

        // ---- targeted exchange reduction over the 16 k-split lanes ----
        const bool hi8 = (s & 8) != 0;
        float r32[8][4];
        #pragma unroll
        for (int bb = 0; bb < 8; ++bb)
            #pragma unroll
            for (int ch = 0; ch < 4; ++ch) {
                float mine = hi8 ? a64[bb][4 + ch] : a64[bb][ch];
                float oth  = hi8 ? a64[bb][ch]     : a64[bb][4 + ch];
                r32[bb][ch] = mine + __shfl_xor_sync(0xffffffffu, oth, 8);
            }
        const bool hi4 = (s & 4) != 0;
        float r16[4][4];
        #pragma unroll
        for (int bl = 0; bl < 4; ++bl)
            #pragma unroll
            for (int ch = 0; ch < 4; ++ch) {
                float mine = hi4 ? r32[bl + 4][ch] : r32[bl][ch];
                float oth  = hi4 ? r32[bl][ch]     : r32[bl + 4][ch];
                r16[bl][ch] = mine + __shfl_xor_sync(0xffffffffu, oth, 4);
            }
        const bool hi2 = (s & 2) != 0;
        float r8[2][4];
        #pragma unroll
        for (int bl = 0; bl < 2; ++bl)
            #pragma unroll
            for (int ch = 0; ch < 4; ++ch) {
                float mine = hi2 ? r16[bl + 2][ch] : r16[bl][ch];
                float oth  = hi2 ? r16[bl][ch]     : r16[bl + 2][ch];
                r8[bl][ch] = mine + __shfl_xor_sync(0xffffffffu, oth, 2);
            }
        const bool hi1 = (s & 1) != 0;
        float r4v[4];
        #pragma unroll
        for (int ch = 0; ch < 4; ++ch) {
            float mine = hi1 ? r8[1][ch] : r8[0][ch];
            float oth  = hi1 ? r8[0][ch] : r8[1][ch];
            r4v[ch] = mine + __shfl_xor_sync(0xffffffffu, oth, 1);
        }

        // ---- activations + state update ----
        const float rg = fast_sigmoid(r4v[0] + c_br);
        const float cg = fast_sigmoid(r4v[1] + c_bi);
        const float ng = fast_tanh(r4v[2] + c_bni + rg * (r4v[3] + c_bnh));
        const float hold = hbuf[myb * STR + jcol];
        const float hnew = ng + cg * (hold - ng);

        g_h[dir][par ^ 1][myb * HH + jcol] = hnew;
        out[((size_t)t * BB + myb) * (2 * HH) + dir * HH + jcol] = hnew;

        GBAR(g);                              // group stores complete
        if (leader) net_arrive(dir, g, grpIdx);
    }
#undef GEMM_ITER
}

// ----------------------------------------------------------------------------
// Launch. Input order: x, Wri_f,Wci_f,Wni_f,Wrh_f,Wch_f,Wnh_f,br_f,bi_f,bni_f,
// bnh_f, Wri_b,Wci_b,Wni_b,Wrh_b,Wch_b,Wnh_b,br_b,bi_b,bni_b,bnh_b
// ----------------------------------------------------------------------------
extern "C" void kernel_launch(void* const* d_in, const int* in_sizes, int n_in,
                              void* d_out, int out_size)
{
    (void)in_sizes; (void)n_in; (void)out_size;

    Args a;
    a.x = (const float*)d_in[0];
    a.Wxi[0][0] = (const float*)d_in[1];
    a.Wxi[0][1] = (const float*)d_in[2];
    a.Wxi[0][2] = (const float*)d_in[3];
    a.Whh[0][0] = (const float*)d_in[4];
    a.Whh[0][1] = (const float*)d_in[5];
    a.Whh[0][2] = (const float*)d_in[6];
    a.br [0] = (const float*)d_in[7];
    a.bi [0] = (const float*)d_in[8];
    a.bni[0] = (const float*)d_in[9];
    a.bnh[0] = (const float*)d_in[10];
    a.Wxi[1][0] = (const float*)d_in[11];
    a.Wxi[1][1] = (const float*)d_in[12];
    a.Wxi[1][2] = (const float*)d_in[13];
    a.Whh[1][0] = (const float*)d_in[14];
    a.Whh[1][1] = (const float*)d_in[15];
    a.Whh[1][2] = (const float*)d_in[16];
    a.br [1] = (const float*)d_in[17];
    a.bi [1] = (const float*)d_in[18];
    a.bni[1] = (const float*)d_in[19];
    a.bnh[1] = (const float*)d_in[20];
    a.out = (float*)d_out;

    const int smem = (48 * STR + 64 * STR) * (int)sizeof(float);   // ~226 KB
    cudaFuncSetAttribute(gru_fused, cudaFuncAttributeMaxDynamicSharedMemorySize, smem);
    gru_fused<<<2 * NB, 256, smem>>>(a);
}